// round 12
// baseline (speedup 1.0000x reference)
#include <cuda_runtime.h>
#include <cstdint>

// Problem constants
constexpr int B_  = 4;
constexpr int T_  = 2048;
constexpr int C_  = 1024;
constexpr int H_  = 16;
constexpr int HD_ = 64;
constexpr int M_  = B_ * T_;      // 8192 tokens
constexpr int NQKV = 3 * C_;      // 3072

// Scratch (device globals: allocation-free rule)
// All hold tf32-pre-rounded values. GEMM A-operands (g_x, g_y) use a
// within-16-group K permutation p(r) = (r&3)*4 + (r>>2) (self-inverse).
// Weights g_wa/g_wp are stored TRANSPOSED [NTOT][K] with the same K
// permutation. g_k uses a within-8-group d permutation
// dp(d) = (d&~7)|((d&3)<<1)|((d>>2)&1) so attention K fragments pair into
// LDS.64 loads.
__device__ float g_x [M_ * C_];        // rounded x, K-permuted, [M][K]
__device__ float g_wa[C_ * NQKV];      // rounded W_attn^T, K-permuted, [NQKV][K]
__device__ float g_wp[C_ * C_];        // rounded W_proj^T, K-permuted, [C][K]
__device__ float g_q[B_ * H_ * T_ * HD_];
__device__ float g_k[B_ * H_ * T_ * HD_];   // d-permuted within 8-groups
__device__ float g_v[B_ * H_ * T_ * HD_];
__device__ float g_y[B_ * T_ * C_];    // attention out, rounded, K-permuted

__device__ __forceinline__ uint32_t f2tf32(float x) {
    uint32_t u;
    asm("cvt.rna.tf32.f32 %0, %1;" : "=r"(u) : "f"(x));
    return u;
}
__device__ __forceinline__ float rtf(float x) { return __uint_as_float(f2tf32(x)); }

__device__ __forceinline__ float ex2_approx(float x) {
    float y;
    asm("ex2.approx.ftz.f32 %0, %1;" : "=f"(y) : "f"(x));
    return y;
}

__device__ __forceinline__ void cp_async16(void* smem_ptr, const void* gptr) {
    uint32_t sa = (uint32_t)__cvta_generic_to_shared(smem_ptr);
    asm volatile("cp.async.cg.shared.global [%0], [%1], 16;\n" :: "r"(sa), "l"(gptr));
}
__device__ __forceinline__ void cp_commit() {
    asm volatile("cp.async.commit_group;\n");
}
__device__ __forceinline__ void cp_wait0() {
    asm volatile("cp.async.wait_group 0;\n");
}
__device__ __forceinline__ void cp_wait1() {
    asm volatile("cp.async.wait_group 1;\n");
}

__device__ __forceinline__ void mma_tf32(float* d, const uint32_t* a, const uint32_t* b, const float* c) {
    asm volatile(
        "mma.sync.aligned.m16n8k8.row.col.f32.tf32.tf32.f32 "
        "{%0,%1,%2,%3}, {%4,%5,%6,%7}, {%8,%9}, {%10,%11,%12,%13};\n"
        : "=f"(d[0]), "=f"(d[1]), "=f"(d[2]), "=f"(d[3])
        : "r"(a[0]), "r"(a[1]), "r"(a[2]), "r"(a[3]),
          "r"(b[0]), "r"(b[1]),
          "f"(c[0]), "f"(c[1]), "f"(c[2]), "f"(c[3]));
}

// ---------------------------------------------------------------------------
// Prep (one-time):
//  - g_x:  tf32-round + K-permute x (row-major [M][K], 16-group transpose)
//  - g_wa/g_wp: tf32-round + TRANSPOSE W to [NTOT][K] + K-permute.
// Physical float4 #q of each 16-group holds logical k {q, q+4, q+8, q+12}.
// ---------------------------------------------------------------------------
constexpr int NXG  = M_ * C_ / 16;       // 16-float groups of x
constexpr int NWAG = NQKV * (C_ / 16);   // (n, kgroup) pairs of W_attn
constexpr int NWPG = C_   * (C_ / 16);   // (n, kgroup) pairs of W_proj
constexpr int NPREP = NXG + NWAG + NWPG;

__device__ __forceinline__ void transpose_perm_16(
    const float* __restrict__ W, float* __restrict__ dst, int NTOT, int n, int kg)
{
    float r[16];
    #pragma unroll
    for (int t = 0; t < 16; ++t)
        r[t] = W[(size_t)(kg * 16 + t) * NTOT + n];
    float4* d = reinterpret_cast<float4*>(&dst[(size_t)n * C_ + kg * 16]);
    d[0] = make_float4(rtf(r[0]), rtf(r[4]), rtf(r[8]),  rtf(r[12]));
    d[1] = make_float4(rtf(r[1]), rtf(r[5]), rtf(r[9]),  rtf(r[13]));
    d[2] = make_float4(rtf(r[2]), rtf(r[6]), rtf(r[10]), rtf(r[14]));
    d[3] = make_float4(rtf(r[3]), rtf(r[7]), rtf(r[11]), rtf(r[15]));
}

__global__ __launch_bounds__(256)
void prep_round_kernel(const float* __restrict__ x,
                       const float* __restrict__ wa,
                       const float* __restrict__ wp)
{
    int i = blockIdx.x * blockDim.x + threadIdx.x;
    if (i < NXG) {
        const float4* src = reinterpret_cast<const float4*>(x) + (size_t)i * 4;
        const float4 v0 = src[0], v1 = src[1], v2 = src[2], v3 = src[3];
        float4* dst = reinterpret_cast<float4*>(g_x) + (size_t)i * 4;
        dst[0] = make_float4(rtf(v0.x), rtf(v1.x), rtf(v2.x), rtf(v3.x));
        dst[1] = make_float4(rtf(v0.y), rtf(v1.y), rtf(v2.y), rtf(v3.y));
        dst[2] = make_float4(rtf(v0.z), rtf(v1.z), rtf(v2.z), rtf(v3.z));
        dst[3] = make_float4(rtf(v0.w), rtf(v1.w), rtf(v2.w), rtf(v3.w));
        return;
    }
    if (i < NXG + NWAG) {
        int j  = i - NXG;
        int kg = j / NQKV;          // lanes adjacent in n -> coalesced reads
        int n  = j % NQKV;
        transpose_perm_16(wa, g_wa, NQKV, n, kg);
        return;
    }
    if (i < NPREP) {
        int j  = i - NXG - NWAG;
        int kg = j / C_;
        int n  = j % C_;
        transpose_perm_16(wp, g_wp, C_, n, kg);
    }
}

// ---------------------------------------------------------------------------
// GEMM: C[M, NTOT] = A[M,1024] @ W[1024,NTOT] + bias, cp.async 3-stage pipe.
// BOTH operands K-permuted (A row-major, W transposed) -> every fragment is
// one LDS.128 covering both k8 steps. As/Bs smem: [rows][16], pad-free;
// 128-bit loads conflict-free (bank-group 4*(row&1)+qc distinct per phase).
// MODE 1: A = g_x,  W = g_wa; epilogue scatters tf32-rounded q/k/v.
//         q/v: paired 64-bit stores; k: scalar stores at within-8 permuted d.
// MODE 0: A = g_y,  W = g_wp; epilogue writes fp32 Cout (+bias, 64-bit).
// ---------------------------------------------------------------------------
constexpr int GBM = 128, GBN = 128, GBK = 16, GSTAGES = 3;
constexpr int GA_WORDS = GBM * GBK;              // 2048 per stage
constexpr int GB_WORDS = GBN * GBK;              // 2048 per stage ([n][k])
constexpr int SMEM_GEMM = GSTAGES * (GA_WORDS + GB_WORDS) * 4;  // 49152 B

template<int NTOT, int MODE>
__global__ __launch_bounds__(256)
void gemm_tf32_kernel(const float* __restrict__ bias,
                      float* __restrict__ Cout)
{
    constexpr int K = 1024;
    constexpr int KTILES = K / GBK;

    extern __shared__ float gsm[];
    float* AsBase = gsm;                           // [stage][128 m][16] perm
    float* BsBase = gsm + GSTAGES * GA_WORDS;      // [stage][128 n][16] perm

    const float* A = (MODE == 1) ? g_x  : g_y;
    const float* W = (MODE == 1) ? g_wa : g_wp;    // [NTOT][K] transposed

    const int tid  = threadIdx.x;
    const int warp = tid >> 5;
    const int lane = tid & 31;
    const int wr   = warp >> 1;        // 0..3  (m, 32 rows each)
    const int wc   = warp & 1;         // 0..1  (n, 64 cols each)
    const int qr   = lane >> 2;        // 0..7
    const int qc   = lane & 3;         // 0..3
    const int m0   = blockIdx.y * GBM;
    const int n0   = blockIdx.x * GBN;

    auto issue_tile = [&](int kt, int s) {
        const int k0 = kt * GBK;
        float* As = AsBase + s * GA_WORDS;
        float* Bs = BsBase + s * GB_WORDS;
        #pragma unroll
        for (int it = 0; it < 2; ++it) {
            int idx = tid + it * 256;          // 0..511
            int m   = idx >> 2;                // 0..127
            int q   = idx & 3;                 // 16B chunk (permuted: raw copy)
            cp_async16(&As[m * GBK + q * 4], &A[(size_t)(m0 + m) * K + k0 + q * 4]);
        }
        #pragma unroll
        for (int it = 0; it < 2; ++it) {
            int idx = tid + it * 256;          // 0..511
            int n   = idx >> 2;                // 0..127
            int q   = idx & 3;
            cp_async16(&Bs[n * GBK + q * 4], &W[(size_t)(n0 + n) * K + k0 + q * 4]);
        }
        cp_commit();
    };

    float acc[2][8][4];
    #pragma unroll
    for (int mt = 0; mt < 2; ++mt)
        #pragma unroll
        for (int nt = 0; nt < 8; ++nt)
            #pragma unroll
            for (int ci = 0; ci < 4; ++ci) acc[mt][nt][ci] = 0.f;

    issue_tile(0, 0);
    issue_tile(1, 1);

    int s = 0;
    for (int kt = 0; kt < KTILES; ++kt) {
        cp_wait1();                 // stage s complete (<=1 group outstanding)
        __syncthreads();            // all CTA loads visible; prior reads of write-target done
        if (kt + 2 < KTILES) issue_tile(kt + 2, (s + 2) % GSTAGES);

        const float* As = AsBase + s * GA_WORDS;
        const float* Bs = BsBase + s * GB_WORDS;

        // A fragments, both ks steps: 4 LDS.128. Component j = logical k j*4+qc.
        uint32_t af[2][2][4];   // [mt][ks][reg]
        #pragma unroll
        for (int mt = 0; mt < 2; ++mt) {
            const int mrow = wr * 32 + mt * 16 + qr;
            const uint4 va = *reinterpret_cast<const uint4*>(&As[(mrow    ) * GBK + qc * 4]);
            const uint4 vb = *reinterpret_cast<const uint4*>(&As[(mrow + 8) * GBK + qc * 4]);
            af[mt][0][0] = va.x;  af[mt][0][2] = va.y;   // ks0: k=qc, qc+4
            af[mt][1][0] = va.z;  af[mt][1][2] = va.w;   // ks1: k=8+qc, 12+qc
            af[mt][0][1] = vb.x;  af[mt][0][3] = vb.y;   // row +8
            af[mt][1][1] = vb.z;  af[mt][1][3] = vb.w;
        }

        // B fragments, both ks steps: 8 LDS.128.
        uint32_t bf[2][8][2];   // [ks][nt][reg]
        #pragma unroll
        for (int nt = 0; nt < 8; ++nt) {
            const int ncol = wc * 64 + nt * 8 + qr;
            const uint4 vb = *reinterpret_cast<const uint4*>(&Bs[ncol * GBK + qc * 4]);
            bf[0][nt][0] = vb.x;  bf[0][nt][1] = vb.y;   // ks0: k=qc, qc+4
            bf[1][nt][0] = vb.z;  bf[1][nt][1] = vb.w;   // ks1: k=8+qc, 12+qc
        }

        #pragma unroll
        for (int ks = 0; ks < 2; ++ks) {
            #pragma unroll
            for (int nt = 0; nt < 8; ++nt) {
                mma_tf32(acc[0][nt], af[0][ks], bf[ks][nt], acc[0][nt]);
                mma_tf32(acc[1][nt], af[1][ks], bf[ks][nt], acc[1][nt]);
            }
        }
        s = (s + 1) % GSTAGES;
    }

    // Epilogue: ci pairs (0,1)/(2,3) are adjacent n -> fused 64-bit stores,
    // except K scatter which stores scalar at within-8 permuted d.
    #pragma unroll
    for (int mt = 0; mt < 2; ++mt) {
        #pragma unroll
        for (int nt = 0; nt < 8; ++nt) {
            const int n  = n0 + wc * 64 + nt * 8 + qc * 2;   // even
            const float b0 = bias[n], b1 = bias[n + 1];
            #pragma unroll
            for (int half = 0; half < 2; ++half) {           // half=0: ci 0,1; half=1: ci 2,3
                const int m = m0 + wr * 32 + mt * 16 + qr + half * 8;
                const float v0 = acc[mt][nt][half * 2 + 0] + b0;
                const float v1 = acc[mt][nt][half * 2 + 1] + b1;
                if (MODE == 0) {
                    *reinterpret_cast<float2*>(&Cout[(size_t)m * NTOT + n]) =
                        make_float2(v0, v1);
                } else {
                    // Pair shares (which, h): d = (n&1023)&63 and d+1 <= 63 always
                    int bb = m / T_, t = m % T_;
                    int which = n >> 10;           // 0:q 1:k 2:v
                    int c = n & 1023;
                    int h = c >> 6, d = c & 63;
                    size_t base = (((size_t)bb * H_ + h) * T_ + t) * HD_;
                    if (which == 1) {
                        // K: within-8 d-permutation dp = (d&~7)|((d&3)<<1)|((d>>2)&1)
                        const int d1 = d + 1;
                        const int dp0 = (d  & ~7) | ((d  & 3) << 1) | ((d  >> 2) & 1);
                        const int dp1 = (d1 & ~7) | ((d1 & 3) << 1) | ((d1 >> 2) & 1);
                        g_k[base + dp0] = rtf(v0);
                        g_k[base + dp1] = rtf(v1);
                    } else {
                        float* dst = (which == 0) ? g_q : g_v;
                        *reinterpret_cast<float2*>(&dst[base + d]) =
                            make_float2(rtf(v0), rtf(v1));
                    }
                }
            }
        }
    }
}

// ---------------------------------------------------------------------------
// Flash attention: one block per (b, h, qtile of 256 rows). 256 threads,
// 8 warps, each warp owns 32 q-rows (2 m-tiles of 16). KV tiles of 64,
// cp.async double-buffer. Online softmax in BASE-2 domain (log2e folded into
// the Q scale; bare ex2.approx). S and P*V via tf32 mma; P re-fragmented via
// smem (paired 64-bit stores). Q/K/V tf32-pre-rounded.
// LPT scheduling: qtile = gridDim.x-1-blockIdx.x (heavy CTAs first).
// Diagonal-band warp skip: fully-masked warp-tile == exact no-op -> skip.
// QK fragment vectorization (this round):
//  - Qs columns interleaved within 16-blocks: qp = (q&~15)|((q&7)<<1)|((q>>3)&1)
//    -> (rm, rm+8) adjacent -> A-frags are LDS.64. Banks: 8qc+2qr distinct/phase.
//  - g_k d-permuted within 8-groups (see GEMM epilogue) -> (d, d+4) adjacent
//    -> K-frags are LDS.64. LDK=72: banks 8qr+2qc distinct/phase.
// Epilogue writes tf32-rounded, K-PERMUTED g_y (proj GEMM A operand).
// Per-array smem strides (conflict-free fragment reads):
//   Qs [64 d][256 q]    stride 264 (%32=8), q interleaved
//   Ps [256 q][64 kv]   stride 68  (%32=4)
//   Ks [2][64 kv][64 d] stride 72, d permuted within 8-groups
//   Vs [2][64 kv][64 d] stride 72
// ---------------------------------------------------------------------------
constexpr int ABQ = 256, ABKV = 64;
constexpr int LDQ = ABQ + 8;    // 264
constexpr int LDP = ABKV + 4;   // 68
constexpr int LDK = HD_ + 8;    // 72 (64-bit paired loads need %32=8)
constexpr int LDV = HD_ + 8;    // 72
constexpr int QS_WORDS = HD_  * LDQ;        // 16896
constexpr int PS_WORDS = ABQ  * LDP;        // 17408
constexpr int KS_WORDS = ABKV * LDK;        // per stage 4608
constexpr int VS_WORDS = ABKV * LDV;        // per stage 4608
constexpr int SMEM_ATTN = (QS_WORDS + PS_WORDS + 2 * KS_WORDS + 2 * VS_WORDS) * 4; // 210944 B

// 1/sqrt(HD) * log2(e): S comes out of the mma pre-scaled for base-2 softmax.
#define QSCALE 0.180336880573351f

__global__ __launch_bounds__(256)
void flash_attn_kernel()
{
    extern __shared__ float smf[];
    uint32_t* Qs = reinterpret_cast<uint32_t*>(smf);                 // [d][qp] tf32 bits
    uint32_t* Ps = Qs + QS_WORDS;                                    // [q][kv] tf32 bits
    float*    Ks = smf + QS_WORDS + PS_WORDS;                        // [2][kv][dp] pre-rounded
    float*    Vs = Ks + 2 * KS_WORDS;                                // [2][kv][d] pre-rounded

    const int qtile = (int)(gridDim.x - 1 - blockIdx.x);  // LPT: 7..0
    const int h     = blockIdx.y;
    const int b     = blockIdx.z;
    const int tid   = threadIdx.x;
    const int warp  = tid >> 5;         // 0..7
    const int lane  = tid & 31;
    const int qr    = lane >> 2;
    const int qc    = lane & 3;

    const size_t bh    = ((size_t)b * H_ + h) * T_ * HD_;
    const int    qbase = qtile * ABQ;
    const int    jmax  = 4 * qtile + 3; // inclusive; kv tiles of 64

    auto issue_kv = [&](int j, int s) {
        const size_t kb = bh + (size_t)j * ABKV * HD_;
        float* Kst = Ks + s * KS_WORDS;
        float* Vst = Vs + s * VS_WORDS;
        #pragma unroll
        for (int it = 0; it < 4; ++it) {
            int idx = tid + it * 256;    // 0..1023
            int kv  = idx >> 4;          // 0..63
            int dq  = idx & 15;          // d-quad (raw copy: preserves g_k perm)
            cp_async16(&Kst[kv * LDK + dq * 4], &g_k[kb + (size_t)kv * HD_ + dq * 4]);
            cp_async16(&Vst[kv * LDV + dq * 4], &g_v[kb + (size_t)kv * HD_ + dq * 4]);
        }
        cp_commit();
    };

    issue_kv(0, 0);

    // Load Q tile scaled by QSCALE, transpose to [d][qp] with q interleaved
    // within 16-blocks so (rm, rm+8) land adjacent.
    #pragma unroll
    for (int it = 0; it < 16; ++it) {
        int idx = tid + it * 256;       // 0..4095
        int q   = idx >> 4;             // 0..255
        int dg  = idx & 15;             // d group (x4)
        int qp  = (q & ~15) | ((q & 7) << 1) | ((q >> 3) & 1);
        const float4 v = *reinterpret_cast<const float4*>(
            &g_q[bh + (size_t)(qbase + q) * HD_ + dg * 4]);
        Qs[(dg * 4 + 0) * LDQ + qp] = f2tf32(v.x * QSCALE);
        Qs[(dg * 4 + 1) * LDQ + qp] = f2tf32(v.y * QSCALE);
        Qs[(dg * 4 + 2) * LDQ + qp] = f2tf32(v.z * QSCALE);
        Qs[(dg * 4 + 3) * LDQ + qp] = f2tf32(v.w * QSCALE);
    }

    float m_run[2][2], l_run[2][2];
    #pragma unroll
    for (int mt = 0; mt < 2; ++mt)
        #pragma unroll
        for (int r = 0; r < 2; ++r) { m_run[mt][r] = -1e30f; l_run[mt][r] = 0.f; }

    float of[2][8][4];
    #pragma unroll
    for (int mt = 0; mt < 2; ++mt)
        #pragma unroll
        for (int nt = 0; nt < 8; ++nt)
            #pragma unroll
            for (int ci = 0; ci < 4; ++ci) of[mt][nt][ci] = 0.f;

    const int rw = warp * 32;           // warp's q-row base (2 m-tiles of 16)

    for (int j = 0; j <= jmax; ++j) {
        const int s = j & 1;
        cp_wait0();
        __syncthreads();                // stage s visible; prev reads of s^1 done
        if (j < jmax) issue_kv(j + 1, s ^ 1);

        // Warp-tile fully above causal boundary -> exact no-op; skip all compute.
        if (j * ABKV > qbase + rw + 31) continue;

        const float* Kst = Ks + s * KS_WORDS;
        const float* Vst = Vs + s * VS_WORDS;

        // S' = (Q*QSCALE) @ K^T  — 32x64 per warp (2 m-tiles), base-2 scaled
        float sf[2][8][4];
        #pragma unroll
        for (int mt = 0; mt < 2; ++mt)
            #pragma unroll
            for (int nt = 0; nt < 8; ++nt)
                #pragma unroll
                for (int ci = 0; ci < 4; ++ci) sf[mt][nt][ci] = 0.f;

        #pragma unroll
        for (int kk = 0; kk < 8; ++kk) {
            uint32_t a[2][4];
            #pragma unroll
            for (int mt = 0; mt < 2; ++mt) {
                // qp(rm) = rw + mt*16 + 2*qr (bit3 of rm is 0); qp(rm+8) = +1
                const int qpb = rw + mt * 16 + qr * 2;
                const uint2 va = *reinterpret_cast<const uint2*>(
                    &Qs[(kk * 8 + qc    ) * LDQ + qpb]);
                const uint2 vb = *reinterpret_cast<const uint2*>(
                    &Qs[(kk * 8 + qc + 4) * LDQ + qpb]);
                a[mt][0] = va.x;  a[mt][1] = va.y;
                a[mt][2] = vb.x;  a[mt][3] = vb.y;
            }
            #pragma unroll
            for (int nt = 0; nt < 8; ++nt) {
                const int ncol = nt * 8 + qr;   // kv index
                // g_k perm: (d=kk*8+qc, d+4) at physical kk*8 + 2qc, +1
                const uint2 vk = *reinterpret_cast<const uint2*>(
                    &Kst[ncol * LDK + kk * 8 + qc * 2]);
                uint32_t bb[2] = {vk.x, vk.y};
                mma_tf32(sf[0][nt], a[0], bb, sf[0][nt]);
                mma_tf32(sf[1][nt], a[1], bb, sf[1][nt]);
            }
        }

        // Causal mask on diagonal-straddling kv tiles (exact global compare)
        if (j >= 4 * qtile) {
            const int kvb = j * ABKV;
            #pragma unroll
            for (int mt = 0; mt < 2; ++mt)
                #pragma unroll
                for (int nt = 0; nt < 8; ++nt)
                    #pragma unroll
                    for (int ci = 0; ci < 4; ++ci) {
                        int kvg = kvb + nt * 8 + qc * 2 + (ci & 1);
                        int qg  = qbase + rw + mt * 16 + qr + ((ci >= 2) ? 8 : 0);
                        if (kvg > qg) sf[mt][nt][ci] = -1e30f;
                    }
        }

        // Online softmax, base-2 domain (regs {0,1}->row +qr, {2,3}->+qr+8)
        #pragma unroll
        for (int mt = 0; mt < 2; ++mt) {
            float rmax[2] = {-1e30f, -1e30f};
            #pragma unroll
            for (int nt = 0; nt < 8; ++nt) {
                rmax[0] = fmaxf(rmax[0], fmaxf(sf[mt][nt][0], sf[mt][nt][1]));
                rmax[1] = fmaxf(rmax[1], fmaxf(sf[mt][nt][2], sf[mt][nt][3]));
            }
            #pragma unroll
            for (int r = 0; r < 2; ++r) {
                rmax[r] = fmaxf(rmax[r], __shfl_xor_sync(0xffffffffu, rmax[r], 1));
                rmax[r] = fmaxf(rmax[r], __shfl_xor_sync(0xffffffffu, rmax[r], 2));
            }
            float mnew[2], alpha[2];
            #pragma unroll
            for (int r = 0; r < 2; ++r) {
                mnew[r]  = fmaxf(m_run[mt][r], rmax[r]);
                alpha[r] = ex2_approx(m_run[mt][r] - mnew[r]);
                m_run[mt][r] = mnew[r];
            }
            float rsum[2] = {0.f, 0.f};
            #pragma unroll
            for (int nt = 0; nt < 8; ++nt) {
                #pragma unroll
                for (int ci = 0; ci < 4; ++ci) {
                    int r = (ci >= 2);
                    float p = ex2_approx(sf[mt][nt][ci] - mnew[r]);
                    sf[mt][nt][ci] = p;
                    rsum[r] += p;
                }
            }
            #pragma unroll
            for (int r = 0; r < 2; ++r) {
                rsum[r] += __shfl_xor_sync(0xffffffffu, rsum[r], 1);
                rsum[r] += __shfl_xor_sync(0xffffffffu, rsum[r], 2);
                l_run[mt][r] = l_run[mt][r] * alpha[r] + rsum[r];
            }
            #pragma unroll
            for (int nt = 0; nt < 8; ++nt) {
                of[mt][nt][0] *= alpha[0];
                of[mt][nt][1] *= alpha[0];
                of[mt][nt][2] *= alpha[1];
                of[mt][nt][3] *= alpha[1];
            }
        }

        // P -> smem (warp-private rows), paired 64-bit stores.
        #pragma unroll
        for (int mt = 0; mt < 2; ++mt)
            #pragma unroll
            for (int nt = 0; nt < 8; ++nt) {
                int rm  = rw + mt * 16 + qr;
                int col = nt * 8 + qc * 2;
                *reinterpret_cast<uint2*>(&Ps[(rm    ) * LDP + col]) =
                    make_uint2(f2tf32(sf[mt][nt][0]), f2tf32(sf[mt][nt][1]));
                *reinterpret_cast<uint2*>(&Ps[(rm + 8) * LDP + col]) =
                    make_uint2(f2tf32(sf[mt][nt][2]), f2tf32(sf[mt][nt][3]));
            }
        __syncwarp();

        #pragma unroll
        for (int kk = 0; kk < 8; ++kk) {
            uint32_t a[2][4];
            #pragma unroll
            for (int mt = 0; mt < 2; ++mt) {
                int rm = rw + mt * 16 + qr;
                a[mt][0] = Ps[(rm    ) * LDP + kk * 8 + qc];
                a[mt][1] = Ps[(rm + 8) * LDP + kk * 8 + qc];
                a[mt][2] = Ps[(rm    ) * LDP + kk * 8 + qc + 4];
                a[mt][3] = Ps[(rm + 8) * LDP + kk * 8 + qc + 4];
            }
            #pragma unroll
            for (int nt = 0; nt < 8; ++nt) {
                uint32_t bb[2];
                int ncol = nt * 8 + qr;     // d index
                bb[0] = __float_as_uint(Vst[(kk * 8 + qc    ) * LDV + ncol]);
                bb[1] = __float_as_uint(Vst[(kk * 8 + qc + 4) * LDV + ncol]);
                mma_tf32(of[0][nt], a[0], bb, of[0][nt]);
                mma_tf32(of[1][nt], a[1], bb, of[1][nt]);
            }
        }
    }

    // Epilogue: O /= l, tf32-round, write K-PERMUTED g_y[B,T,C] (scalar
    // stores: permuted cols p(c) aren't adjacent). p(r) = (r&3)*4 + (r>>2).
    #pragma unroll
    for (int mt = 0; mt < 2; ++mt) {
        float inv_l[2] = {1.f / l_run[mt][0], 1.f / l_run[mt][1]};
        #pragma unroll
        for (int nt = 0; nt < 8; ++nt) {
            #pragma unroll
            for (int ci = 0; ci < 4; ++ci) {
                const int r   = (ci >= 2);
                const int row = rw + mt * 16 + qr + (r ? 8 : 0);
                const int c   = h * HD_ + nt * 8 + qc * 2 + (ci & 1);  // logical col
                const int cp  = (c & ~15) | (((c & 3) << 2) | ((c & 15) >> 2));
                g_y[((size_t)b * T_ + qbase + row) * C_ + cp] =
                    rtf(of[mt][nt][ci] * inv_l[r]);
            }
        }
    }
}

// ---------------------------------------------------------------------------
extern "C" void kernel_launch(void* const* d_in, const int* in_sizes, int n_in,
                              void* d_out, int out_size)
{
    (void)in_sizes; (void)n_in; (void)out_size;
    const float* b_attn = (const float*)d_in[2];
    const float* b_proj = (const float*)d_in[4];
    float* out = (float*)d_out;

    cudaFuncSetAttribute(gemm_tf32_kernel<NQKV, 1>,
                         cudaFuncAttributeMaxDynamicSharedMemorySize, SMEM_GEMM);
    cudaFuncSetAttribute(gemm_tf32_kernel<C_, 0>,
                         cudaFuncAttributeMaxDynamicSharedMemorySize, SMEM_GEMM);
    cudaFuncSetAttribute(flash_attn_kernel,
                         cudaFuncAttributeMaxDynamicSharedMemorySize, SMEM_ATTN);

    // 0) tf32 pre-round: x K-permuted; W_attn/W_proj transposed + K-permuted
    prep_round_kernel<<<(NPREP + 255) / 256, 256>>>(
        (const float*)d_in[0], (const float*)d_in[1], (const float*)d_in[3]);
    // 1) QKV projection + scatter tf32-rounded q/k/v (k d-permuted)
    gemm_tf32_kernel<NQKV, 1><<<dim3(NQKV / 128, M_ / 128), 256, SMEM_GEMM>>>(b_attn, nullptr);
    // 2) Causal flash attention -> g_y [B,T,C] (rounded, K-permuted), LPT order
    flash_attn_kernel<<<dim3(T_ / ABQ, H_, B_), 256, SMEM_ATTN>>>();
    // 3) Output projection
    gemm_tf32_kernel<C_, 0><<<dim3(C_ / 128, M_ / 128), 256, SMEM_GEMM>>>(b_proj, out);
}